// round 1
// baseline (speedup 1.0000x reference)
#include <cuda_runtime.h>
#include <cuda_bf16.h>

#define BATCH     1000000
#define FEAT      128
#define NCLASS    1000
#define NBLOCKS   1184      // 148 SMs * 8 blocks (256 thr) = full occupancy wave
#define NTHREADS  256
#define WARPS_PER_BLOCK (NTHREADS / 32)

// Per-block partial sums (no atomics -> deterministic, no zeroing needed:
// every block writes its slot every launch).
__device__ float g_partials[NBLOCKS];

__global__ __launch_bounds__(NTHREADS) void hinge_main_kernel(
    const float* __restrict__ x,
    const int* __restrict__ labels,
    const float* __restrict__ centers)
{
    const int lane = threadIdx.x & 31;
    const int wid  = threadIdx.x >> 5;
    const int gw   = blockIdx.x * WARPS_PER_BLOCK + wid;
    const int nw   = gridDim.x * WARPS_PER_BLOCK;

    const float4* __restrict__ x4 = reinterpret_cast<const float4*>(x);
    const float4* __restrict__ c4 = reinterpret_cast<const float4*>(centers);

    // margin = ||centers[0] - centers[1]|| / 10  (tiny, L1-hit; every warp computes it)
    float4 ca = __ldg(&c4[lane]);        // centers[0], lane*4 .. lane*4+3
    float4 cb = __ldg(&c4[32 + lane]);   // centers[1]
    float md0 = ca.x - cb.x, md1 = ca.y - cb.y, md2 = ca.z - cb.z, md3 = ca.w - cb.w;
    float ms = md0*md0 + md1*md1 + md2*md2 + md3*md3;
    #pragma unroll
    for (int o = 16; o; o >>= 1) ms += __shfl_xor_sync(0xffffffffu, ms, o);
    const float margin = sqrtf(ms) * 0.1f;

    float acc = 0.0f;
    for (int row = gw; row < BATCH; row += nw) {
        const int lab = __ldg(&labels[row]);
        // x: streamed once -> evict-streaming (keep L1 for the center table)
        float4 xv = __ldcs(&x4[(long long)row * 32 + lane]);
        float4 cv = __ldg (&c4[lab * 32 + lane]);
        float t0 = xv.x - cv.x;
        float t1 = xv.y - cv.y;
        float t2 = xv.z - cv.z;
        float t3 = xv.w - cv.w;
        float s = t0*t0 + t1*t1 + t2*t2 + t3*t3;   // partial ||x - c||^2
        #pragma unroll
        for (int o = 16; o; o >>= 1) s += __shfl_xor_sync(0xffffffffu, s, o);
        if (lane == 0) acc += fmaxf(s - margin, 0.0f);
    }

    // block reduce (lane-0 accumulators only)
    __shared__ float smem[WARPS_PER_BLOCK];
    if (lane == 0) smem[wid] = acc;
    __syncthreads();
    if (threadIdx.x == 0) {
        float s = 0.0f;
        #pragma unroll
        for (int i = 0; i < WARPS_PER_BLOCK; i++) s += smem[i];
        g_partials[blockIdx.x] = s;
    }
}

__global__ void hinge_finalize_kernel(float* __restrict__ out)
{
    __shared__ double sm[256];
    double s = 0.0;
    for (int i = threadIdx.x; i < NBLOCKS; i += 256) s += (double)g_partials[i];
    sm[threadIdx.x] = s;
    __syncthreads();
    #pragma unroll
    for (int o = 128; o; o >>= 1) {
        if (threadIdx.x < o) sm[threadIdx.x] += sm[threadIdx.x + o];
        __syncthreads();
    }
    if (threadIdx.x == 0) {
        // reference: sum / (batch * 2 * 2)
        out[0] = (float)(sm[0] / (double)(4.0 * (double)BATCH));
    }
}

extern "C" void kernel_launch(void* const* d_in, const int* in_sizes, int n_in,
                              void* d_out, int out_size)
{
    const float* x       = (const float*)d_in[0];   // [1e6, 128] f32
    const int*   labels  = (const int*)  d_in[1];   // [1e6] i32
    const float* centers = (const float*)d_in[2];   // [1000, 128] f32
    float*       out     = (float*)d_out;           // scalar f32

    hinge_main_kernel<<<NBLOCKS, NTHREADS>>>(x, labels, centers);
    hinge_finalize_kernel<<<1, 256>>>(out);
}

// round 2
// speedup vs baseline: 1.0410x; 1.0410x over previous
#include <cuda_runtime.h>
#include <cuda_bf16.h>

#define BATCH     1000000
#define FEAT      128
#define NCLASS    1000
#define NBLOCKS   1184      // 148 SMs * 8 blocks (256 thr) = full occupancy wave
#define NTHREADS  256
#define WARPS_PER_BLOCK (NTHREADS / 32)

// Per-block partial sums (every block writes its slot every launch -> no zeroing).
__device__ float g_partials[NBLOCKS];
// Ticket counter for last-block-done reduction. Reset to 0 by the last block
// each launch, so graph replays see a clean state. Deterministic: the final
// reduction is always performed by exactly one block in a fixed order.
__device__ int g_count = 0;

__global__ __launch_bounds__(NTHREADS) void hinge_fused_kernel(
    const float* __restrict__ x,
    const int* __restrict__ labels,
    const float* __restrict__ centers,
    float* __restrict__ out)
{
    const int lane = threadIdx.x & 31;
    const int wid  = threadIdx.x >> 5;
    const int gw   = blockIdx.x * WARPS_PER_BLOCK + wid;
    const int nw   = gridDim.x * WARPS_PER_BLOCK;

    const float4* __restrict__ x4 = reinterpret_cast<const float4*>(x);
    const float4* __restrict__ c4 = reinterpret_cast<const float4*>(centers);

    // margin = ||centers[0] - centers[1]|| / 10  (tiny, L1-hit; every warp computes it)
    float4 ca = __ldg(&c4[lane]);        // centers[0]
    float4 cb = __ldg(&c4[32 + lane]);   // centers[1]
    float md0 = ca.x - cb.x, md1 = ca.y - cb.y, md2 = ca.z - cb.z, md3 = ca.w - cb.w;
    float ms = md0*md0 + md1*md1 + md2*md2 + md3*md3;
    #pragma unroll
    for (int o = 16; o; o >>= 1) ms += __shfl_xor_sync(0xffffffffu, ms, o);
    const float margin = sqrtf(ms) * 0.1f;

    float acc = 0.0f;
    int row = gw;

    // 2-rows-per-iteration mainloop: both label/x/center loads issued up front
    // for doubled memory-level parallelism.
    for (; row + nw < BATCH; row += 2 * nw) {
        const int r0 = row, r1 = row + nw;
        const int lab0 = __ldg(&labels[r0]);
        const int lab1 = __ldg(&labels[r1]);
        float4 xv0 = __ldcs(&x4[(size_t)r0 * 32 + lane]);
        float4 xv1 = __ldcs(&x4[(size_t)r1 * 32 + lane]);
        float4 cv0 = __ldg(&c4[lab0 * 32 + lane]);
        float4 cv1 = __ldg(&c4[lab1 * 32 + lane]);

        float a0 = xv0.x - cv0.x, a1 = xv0.y - cv0.y, a2 = xv0.z - cv0.z, a3 = xv0.w - cv0.w;
        float b0 = xv1.x - cv1.x, b1 = xv1.y - cv1.y, b2 = xv1.z - cv1.z, b3 = xv1.w - cv1.w;
        float s0 = a0*a0 + a1*a1 + a2*a2 + a3*a3;
        float s1 = b0*b0 + b1*b1 + b2*b2 + b3*b3;
        #pragma unroll
        for (int o = 16; o; o >>= 1) {
            s0 += __shfl_xor_sync(0xffffffffu, s0, o);
            s1 += __shfl_xor_sync(0xffffffffu, s1, o);
        }
        if (lane == 0) acc += fmaxf(s0 - margin, 0.0f) + fmaxf(s1 - margin, 0.0f);
    }
    if (row < BATCH) {  // tail (at most one row per warp)
        const int lab = __ldg(&labels[row]);
        float4 xv = __ldcs(&x4[(size_t)row * 32 + lane]);
        float4 cv = __ldg (&c4[lab * 32 + lane]);
        float t0 = xv.x - cv.x, t1 = xv.y - cv.y, t2 = xv.z - cv.z, t3 = xv.w - cv.w;
        float s = t0*t0 + t1*t1 + t2*t2 + t3*t3;
        #pragma unroll
        for (int o = 16; o; o >>= 1) s += __shfl_xor_sync(0xffffffffu, s, o);
        if (lane == 0) acc += fmaxf(s - margin, 0.0f);
    }

    // Block reduce (lane-0 accumulators only).
    __shared__ float smem[WARPS_PER_BLOCK];
    __shared__ bool is_last;
    if (lane == 0) smem[wid] = acc;
    __syncthreads();
    if (threadIdx.x == 0) {
        float s = 0.0f;
        #pragma unroll
        for (int i = 0; i < WARPS_PER_BLOCK; i++) s += smem[i];
        g_partials[blockIdx.x] = s;
        __threadfence();
        int ticket = atomicAdd(&g_count, 1);
        is_last = (ticket == NBLOCKS - 1);
    }
    __syncthreads();

    // Last block reduces all partials (f64, fixed order) and writes the scalar.
    if (is_last) {
        __shared__ double sm[NTHREADS];
        double s = 0.0;
        for (int i = threadIdx.x; i < NBLOCKS; i += NTHREADS)
            s += (double)g_partials[i];
        sm[threadIdx.x] = s;
        __syncthreads();
        #pragma unroll
        for (int o = NTHREADS / 2; o; o >>= 1) {
            if (threadIdx.x < o) sm[threadIdx.x] += sm[threadIdx.x + o];
            __syncthreads();
        }
        if (threadIdx.x == 0) {
            out[0] = (float)(sm[0] / (4.0 * (double)BATCH));
            g_count = 0;   // reset for next launch / graph replay
        }
    }
}

extern "C" void kernel_launch(void* const* d_in, const int* in_sizes, int n_in,
                              void* d_out, int out_size)
{
    const float* x       = (const float*)d_in[0];   // [1e6, 128] f32
    const int*   labels  = (const int*)  d_in[1];   // [1e6] i32
    const float* centers = (const float*)d_in[2];   // [1000, 128] f32
    float*       out     = (float*)d_out;           // scalar f32

    hinge_fused_kernel<<<NBLOCKS, NTHREADS>>>(x, labels, centers, out);
}